// round 3
// baseline (speedup 1.0000x reference)
#include <cuda_runtime.h>

// SKA: out[b, g*8+cw, h, w] = sum_{i,j in 3x3} x[b, g*8+cw, h+i-1, w+j-1] * w[b, cw, i*3+j, h, w]
// x: (8,64,128,128) f32, w: (8,8,9,128,128) f32, out: (8,64,128,128) f32
//
// HBM-bound (AI ~1.4 F/B). Strategy:
//  - block = one (b,h) row; 256 threads: warp k handles cw=k, lanes cover W in float4 chunks
//  - 9 weight float4 kept in registers, reused across the 8 group channels
//  - all global traffic (w loads, x main loads, out stores) warp-coalesced float4
//  - halo columns via scalar loads (L1 hits), h-halo via predicated zero rows

#define SKA_H 128
#define SKA_W 128
#define SKA_C 64
#define SKA_CW 8
#define SKA_G 8

__global__ __launch_bounds__(256, 4)
void SKA_44830868635847_kernel(const float* __restrict__ x,
                               const float* __restrict__ wgt,
                               float* __restrict__ out) {
    const int tid = threadIdx.x;
    const int w0  = (tid & 31) << 2;   // 0,4,...,124
    const int cw  = tid >> 5;          // 0..7 (one warp per cw)
    const int h   = blockIdx.x;        // 0..127
    const int b   = blockIdx.y;        // 0..7

    const long HW = (long)SKA_H * SKA_W;

    // Load the 9 per-position weight vectors for this (b, cw, h, w0..w0+3).
    // Held in registers and reused for all 8 group channels.
    float4 wv[9];
    const float* wp = wgt + (((long)(b * SKA_CW + cw) * 9) * SKA_H + h) * SKA_W + w0;
    #pragma unroll
    for (int k = 0; k < 9; k++) {
        wv[k] = *reinterpret_cast<const float4*>(wp + (long)k * HW);
    }

    const float* xb = x + (long)b * SKA_C * HW;
    float* ob = out + (long)b * SKA_C * HW;

    #pragma unroll
    for (int g = 0; g < SKA_G; g++) {
        const int c = g * SKA_CW + cw;
        const float* xc = xb + (long)c * HW;

        float acc0 = 0.f, acc1 = 0.f, acc2 = 0.f, acc3 = 0.f;

        #pragma unroll
        for (int i = 0; i < 3; i++) {
            const int hh = h + i - 1;
            // r[idx] = x[b, c, hh, w0 + idx - 1]  (idx in 0..5), zero at borders
            float r0, r1, r2, r3, r4, r5;
            if (hh < 0 || hh >= SKA_H) {
                r0 = r1 = r2 = r3 = r4 = r5 = 0.f;
            } else {
                const float* row = xc + (long)hh * SKA_W + w0;
                const float4 m = *reinterpret_cast<const float4*>(row);
                r1 = m.x; r2 = m.y; r3 = m.z; r4 = m.w;
                r0 = (w0 == 0)            ? 0.f : row[-1];
                r5 = (w0 + 4 >= SKA_W)    ? 0.f : row[4];
            }
            // j = 0..2 kernel columns; output position p uses r[p + j]
            {
                const float4 wk = wv[i * 3 + 0];
                acc0 = fmaf(wk.x, r0, acc0);
                acc1 = fmaf(wk.y, r1, acc1);
                acc2 = fmaf(wk.z, r2, acc2);
                acc3 = fmaf(wk.w, r3, acc3);
            }
            {
                const float4 wk = wv[i * 3 + 1];
                acc0 = fmaf(wk.x, r1, acc0);
                acc1 = fmaf(wk.y, r2, acc1);
                acc2 = fmaf(wk.z, r3, acc2);
                acc3 = fmaf(wk.w, r4, acc3);
            }
            {
                const float4 wk = wv[i * 3 + 2];
                acc0 = fmaf(wk.x, r2, acc0);
                acc1 = fmaf(wk.y, r3, acc1);
                acc2 = fmaf(wk.z, r4, acc2);
                acc3 = fmaf(wk.w, r5, acc3);
            }
        }

        float4 o;
        o.x = acc0; o.y = acc1; o.z = acc2; o.w = acc3;
        *reinterpret_cast<float4*>(ob + (long)c * HW + (long)h * SKA_W + w0) = o;
    }
}

extern "C" void kernel_launch(void* const* d_in, const int* in_sizes, int n_in,
                              void* d_out, int out_size) {
    const float* x = (const float*)d_in[0];
    const float* w = (const float*)d_in[1];
    float* out = (float*)d_out;
    (void)in_sizes; (void)n_in; (void)out_size;

    dim3 grid(SKA_H, 8);   // (h, b)
    dim3 block(256);       // 8 warps = 8 cw, 32 lanes * 4 = W
    SKA_44830868635847_kernel<<<grid, block>>>(x, w, out);
}